// round 17
// baseline (speedup 1.0000x reference)
#include <cuda_runtime.h>
#include <cuda_fp16.h>
#include <math.h>
#include <stdint.h>

#define BB 16
#define TT 2048
#define CC 1024
#define HD 128
#define M_TOT (BB*TT)

// Scratch (allocation-free rule -> device globals)
__device__ __half g_xh[(size_t)M_TOT*CC];   // x in fp16
__device__ __half g_q [(size_t)M_TOT*HD];   // pre-scaled by log2e/sqrt(H)
__device__ __half g_k [(size_t)M_TOT*HD];
__device__ __half g_vt[(size_t)M_TOT*HD];   // V transposed [b][d][t]
__device__ __half g_wt[(size_t)3*HD*CC];    // W transposed [mat][h][c]

#define QSCALE 0.12751744f   // log2(e) / sqrt(128)

// ===========================================================================
// Helpers (base-PTX only)
// ===========================================================================
__device__ __forceinline__ uint32_t smem_u32(const void* p) {
    uint32_t a;
    asm("{ .reg .u64 t; cvta.to.shared.u64 t, %1; cvt.u32.u64 %0, t; }" : "=r"(a) : "l"(p));
    return a;
}
__device__ __forceinline__ float ex2(float x) {
    float r;
    asm("ex2.approx.ftz.f32 %0, %1;" : "=f"(r) : "f"(x));
    return r;
}
__device__ __forceinline__ uint32_t h2ex2(uint32_t a) {   // packed fp16x2 2^x
    uint32_t r;
    asm("ex2.approx.f16x2 %0, %1;" : "=r"(r) : "r"(a));
    return r;
}
__device__ __forceinline__ uint32_t f2h2(float lo, float hi) {
    __half2 h = __floats2half2_rn(lo, hi);
    return *reinterpret_cast<uint32_t*>(&h);
}
__device__ __forceinline__ void ldsm4(uint32_t& r0, uint32_t& r1, uint32_t& r2,
                                      uint32_t& r3, uint32_t addr) {
    asm volatile("ldmatrix.sync.aligned.m8n8.x4.shared.b16 {%0,%1,%2,%3}, [%4];"
                 : "=r"(r0), "=r"(r1), "=r"(r2), "=r"(r3) : "r"(addr));
}
__device__ __forceinline__ void mma_f16(float* c, uint32_t a0, uint32_t a1,
                                        uint32_t a2, uint32_t a3,
                                        uint32_t b0, uint32_t b1) {
    asm volatile(
        "mma.sync.aligned.m16n8k16.row.col.f32.f16.f16.f32 "
        "{%0,%1,%2,%3}, {%4,%5,%6,%7}, {%8,%9}, {%0,%1,%2,%3};"
        : "+f"(c[0]), "+f"(c[1]), "+f"(c[2]), "+f"(c[3])
        : "r"(a0), "r"(a1), "r"(a2), "r"(a3), "r"(b0), "r"(b1));
}
__device__ __forceinline__ void cp16(uint32_t dst, const void* src) {
    asm volatile("{ .reg .u64 g; cvta.to.global.u64 g, %1;"
                 "  cp.async.cg.shared.global [%0], [g], 16; }"
                 :: "r"(dst), "l"(src) : "memory");
}
#define CP_COMMIT() asm volatile("cp.async.commit_group;" ::: "memory")
#define CP_WAIT(n)  asm volatile("cp.async.wait_group %0;" :: "n"(n) : "memory")

// ===========================================================================
// Prep: (a) x -> fp16 (blocks [0, XBLKS)), (b) W transpose -> fp16
// ===========================================================================
#define XBLKS ((M_TOT * CC) / 2048)     // 16384 blocks, 8 floats/thread

__global__ void prep_kernel(const float* __restrict__ x,
                            const float* __restrict__ Wk,
                            const float* __restrict__ Wq,
                            const float* __restrict__ Wv)
{
    __shared__ float tile[32][33];
    const int bid = blockIdx.x;
    if (bid < XBLKS) {
        size_t base = ((size_t)bid * 256 + threadIdx.x) * 8;
        float4 a = *(const float4*)(x + base);
        float4 b = *(const float4*)(x + base + 4);
        uint4 h = make_uint4(f2h2(a.x, a.y), f2h2(a.z, a.w),
                             f2h2(b.x, b.y), f2h2(b.z, b.w));
        *(uint4*)(g_xh + base) = h;
        return;
    }
    const int r = bid - XBLKS;
    const int c0 = (r & 31) * 32;
    const int h0 = ((r >> 5) & 3) * 32;
    const int mz = r >> 7;
    const float* W = (mz == 0) ? Wk : (mz == 1) ? Wq : Wv;
    const int t = threadIdx.x;
    const int tx = t & 31, ty = t >> 5;

    #pragma unroll
    for (int i = 0; i < 4; i++)
        tile[ty + 8 * i][tx] = W[(size_t)(c0 + ty + 8 * i) * HD + h0 + tx];
    __syncthreads();
    #pragma unroll
    for (int i = 0; i < 4; i++) {
        int h = h0 + ty + 8 * i;
        int c = c0 + tx;
        g_wt[((size_t)mz * HD + h) * CC + c] = __float2half_rn(tile[tx][ty + 8 * i]);
    }
}

__global__ void noop_kernel() {}   // rotate ncu capture slot

// ===========================================================================
// Projection GEMM (mma.sync fp16), 3-stage cp.async pipeline.
// grid 768: bid = mtile*3 + mat. CTA 128x128, K in 16 chunks of 64.
// smem: A[3]+B[3] tiles (stride 72 halfs) = 110592 B -> 2 CTAs/SM.
// V (mat 2) epilogue: transpose staged through smem -> STG.128 coalesced.
// ===========================================================================
#define PSTR 72
#define PT_HALFS (128 * PSTR)                 // 9216
#define PT_B (PT_HALFS * 2)                   // 18432
#define PROJ_SMEM (6 * PT_B)                  // 110592

__global__ __launch_bounds__(256, 2) void proj_kernel()
{
    extern __shared__ __align__(16) __half psm[];
    const uint32_t uA = smem_u32(psm);
    const uint32_t uB = uA + 3 * PT_B;

    const int t = threadIdx.x, lane = t & 31, wid = t >> 5;
    const int wm = wid & 1, wn = wid >> 1;
    const int mat = (int)blockIdx.x % 3;
    const int m0 = ((int)blockIdx.x / 3) * 128;
    const __half* xh = g_xh + (size_t)m0 * CC;
    const __half* wg = g_wt + (size_t)mat * HD * CC;

    float c[4][4][4];
    #pragma unroll
    for (int i = 0; i < 4; i++)
        #pragma unroll
        for (int j = 0; j < 4; j++)
            #pragma unroll
            for (int r = 0; r < 4; r++) c[i][j][r] = 0.0f;

    // ---- prologue: chunks 0 and 1 ----
    #pragma unroll
    for (int pc = 0; pc < 2; pc++) {
        const uint32_t dA = uA + pc * PT_B;
        const uint32_t dB = uB + pc * PT_B;
        const int co = pc * 64;
        #pragma unroll
        for (int i = 0; i < 4; i++) {
            int idx = t + 256 * i;
            int row = idx >> 3, cc = idx & 7;
            cp16(dA + (row * PSTR + cc * 8) * 2, xh + (size_t)row * CC + co + cc * 8);
            cp16(dB + (row * PSTR + cc * 8) * 2, wg + (size_t)row * CC + co + cc * 8);
        }
        CP_COMMIT();
    }

    for (int ch = 0; ch < 16; ch++) {
        const int s = ch % 3;
        if (ch >= 14) { CP_WAIT(0); } else { CP_WAIT(1); }
        __syncthreads();

        if (ch < 14) {   // issue chunk ch+2 (2 chunks of load slack)
            const int s2 = (ch + 2) % 3;
            const uint32_t dA = uA + s2 * PT_B;
            const uint32_t dB = uB + s2 * PT_B;
            const int co = (ch + 2) * 64;
            #pragma unroll
            for (int i = 0; i < 4; i++) {
                int idx = t + 256 * i;
                int row = idx >> 3, cc = idx & 7;
                cp16(dA + (row * PSTR + cc * 8) * 2, xh + (size_t)row * CC + co + cc * 8);
                cp16(dB + (row * PSTR + cc * 8) * 2, wg + (size_t)row * CC + co + cc * 8);
            }
            CP_COMMIT();
        }

        const uint32_t sAb = uA + s * PT_B;
        const uint32_t sBb = uB + s * PT_B;
        #pragma unroll
        for (int k0 = 0; k0 < 64; k0 += 16) {
            uint32_t a[4][4];
            #pragma unroll
            for (int mt = 0; mt < 4; mt++) {
                int row = wm * 64 + mt * 16 + ((lane >> 3) & 1) * 8 + (lane & 7);
                int col = k0 + (lane >> 4) * 8;
                ldsm4(a[mt][0], a[mt][1], a[mt][2], a[mt][3],
                      sAb + (row * PSTR + col) * 2);
            }
            uint32_t b[4][2];
            #pragma unroll
            for (int p = 0; p < 2; p++) {
                int row = wn * 32 + p * 16 + ((lane >> 4) & 1) * 8 + (lane & 7);
                int col = k0 + ((lane >> 3) & 1) * 8;
                uint32_t r0, r1, r2, r3;
                ldsm4(r0, r1, r2, r3, sBb + (row * PSTR + col) * 2);
                b[2 * p][0] = r0; b[2 * p][1] = r1;
                b[2 * p + 1][0] = r2; b[2 * p + 1][1] = r3;
            }
            #pragma unroll
            for (int mt = 0; mt < 4; mt++)
                #pragma unroll
                for (int nt = 0; nt < 4; nt++)
                    mma_f16(c[mt][nt], a[mt][0], a[mt][1], a[mt][2], a[mt][3],
                            b[nt][0], b[nt][1]);
        }
    }

    // ---- epilogue ----
    if (mat < 2) {
        const float sc = (mat == 1) ? QSCALE : 1.0f;
        __half* og = (mat == 0 ? g_k : g_q) + (size_t)m0 * HD;
        #pragma unroll
        for (int mt = 0; mt < 4; mt++)
            #pragma unroll
            for (int nt = 0; nt < 4; nt++) {
                int r1 = wm * 64 + mt * 16 + (lane >> 2);
                int col = wn * 32 + nt * 8 + 2 * (lane & 3);
                *(uint32_t*)&og[(size_t)r1 * HD + col] =
                    f2h2(c[mt][nt][0] * sc, c[mt][nt][1] * sc);
                *(uint32_t*)&og[(size_t)(r1 + 8) * HD + col] =
                    f2h2(c[mt][nt][2] * sc, c[mt][nt][3] * sc);
            }
    } else {
        // V: stage [m][h] fp16 in smem, then write g_vt[h][m] coalesced
        const int SVT = 136;                       // halfs per staged row
        __half* sv = psm + PT_HALFS;               // reuse buffer A1 region
        #pragma unroll
        for (int mt = 0; mt < 4; mt++)
            #pragma unroll
            for (int nt = 0; nt < 4; nt++) {
                int r1 = wm * 64 + mt * 16 + (lane >> 2);
                int col = wn * 32 + nt * 8 + 2 * (lane & 3);
                *(uint32_t*)&sv[r1 * SVT + col] = f2h2(c[mt][nt][0], c[mt][nt][1]);
                *(uint32_t*)&sv[(r1 + 8) * SVT + col] = f2h2(c[mt][nt][2], c[mt][nt][3]);
            }
        __syncthreads();
        const int bi = m0 >> 11;
        const int t0 = m0 & 2047;
        __half* vt = g_vt + (size_t)bi * HD * TT;
        #pragma unroll
        for (int g = 0; g < 8; g++) {
            int task = wid * 8 + g;                // 0..63
            int col = (task & 7) * 16 + (lane >> 1);
            int r0  = (task >> 3) * 16 + (lane & 1) * 8;
            uint32_t u[4];
            #pragma unroll
            for (int i = 0; i < 4; i++) {
                uint32_t lo = *(const uint16_t*)&sv[(r0 + 2 * i) * SVT + col];
                uint32_t hi = *(const uint16_t*)&sv[(r0 + 2 * i + 1) * SVT + col];
                u[i] = lo | (hi << 16);
            }
            *(uint4*)&vt[(size_t)col * TT + t0 + r0] = make_uint4(u[0], u[1], u[2], u[3]);
        }
    }
}

// ===========================================================================
// Flash attention (mma.sync fp16), causal-pairing balance (grid 8 x BB,
// each CTA runs qtile bx then 15-bx -> 17 iters each, one wave).
// f16x2 ex2 softmax; per-thread l partials (reduced in epilogue);
// vote-gated O rescale. K/V double-buffered cp.async.
// ===========================================================================
#define KSTR 136
#define KV_B (128 * KSTR * 2)
#define VOFF_B KV_B
#define STG_B (2 * KV_B)
#define ATTN_SMEM (2 * STG_B)                 // 139264

__device__ __forceinline__ void attn_smma(float s[8][4], const uint32_t qf[8][4],
                                          uint32_t kbase, int lane)
{
    #pragma unroll
    for (int i = 0; i < 8; i++)
        #pragma unroll
        for (int r = 0; r < 4; r++) s[i][r] = 0.0f;
    #pragma unroll
    for (int k0 = 0; k0 < 128; k0 += 16) {
        const uint32_t* a = qf[k0 >> 4];
        #pragma unroll
        for (int p = 0; p < 4; p++) {
            int row = p * 16 + ((lane >> 4) & 1) * 8 + (lane & 7);
            int col = k0 + ((lane >> 3) & 1) * 8;
            uint32_t b0, b1, b2, b3;
            ldsm4(b0, b1, b2, b3, kbase + (row * KSTR + col) * 2);
            mma_f16(s[2 * p],     a[0], a[1], a[2], a[3], b0, b1);
            mma_f16(s[2 * p + 1], a[0], a[1], a[2], a[3], b2, b3);
        }
    }
}

__device__ __forceinline__ void attn_softmax(float s[8][4],
    uint32_t pL[8], uint32_t pH[8],
    float& m1, float& m2, float& l1, float& l2, float& al1, float& al2,
    bool need_mask, int keybase, int qrow1, int qrow2, int lane)
{
    float mx1 = -INFINITY, mx2 = -INFINITY;
    #pragma unroll
    for (int nt = 0; nt < 8; nt++) {
        #pragma unroll
        for (int j = 0; j < 2; j++) {
            int key = keybase + nt * 8 + 2 * (lane & 3) + j;
            float v1 = s[nt][j];
            float v2 = s[nt][2 + j];
            if (need_mask && key > qrow1) v1 = -INFINITY;
            if (need_mask && key > qrow2) v2 = -INFINITY;
            s[nt][j] = v1; s[nt][2 + j] = v2;
            mx1 = fmaxf(mx1, v1); mx2 = fmaxf(mx2, v2);
        }
    }
    mx1 = fmaxf(mx1, __shfl_xor_sync(0xffffffffu, mx1, 1));
    mx1 = fmaxf(mx1, __shfl_xor_sync(0xffffffffu, mx1, 2));
    mx2 = fmaxf(mx2, __shfl_xor_sync(0xffffffffu, mx2, 1));
    mx2 = fmaxf(mx2, __shfl_xor_sync(0xffffffffu, mx2, 2));
    float mn1 = fmaxf(m1, mx1), mn2 = fmaxf(m2, mx2);

    float su1 = 0.0f, su2 = 0.0f;
    #pragma unroll
    for (int nt = 0; nt < 8; nt++) {
        uint32_t aL = f2h2(s[nt][0] - mn1, s[nt][1] - mn1);   // -inf stays -inf
        uint32_t aH = f2h2(s[nt][2] - mn2, s[nt][3] - mn2);
        pL[nt] = h2ex2(aL);                                    // ex2(-inf) = +0
        pH[nt] = h2ex2(aH);
        float2 fL = __half22float2(*(const __half2*)&pL[nt]);
        float2 fH = __half22float2(*(const __half2*)&pH[nt]);
        su1 += fL.x + fL.y;
        su2 += fH.x + fH.y;
    }
    al1 = ex2(m1 - mn1); al2 = ex2(m2 - mn2);
    m1 = mn1; m2 = mn2;
    l1 = l1 * al1 + su1;            // per-thread partial; quad-reduced at end
    l2 = l2 * al2 + su2;
}

__device__ __forceinline__ void attn_pv(float o[16][4],
    const uint32_t pL[8], const uint32_t pH[8], uint32_t vbase, int lane)
{
    #pragma unroll
    for (int kk = 0; kk < 4; kk++) {
        uint32_t a0 = pL[2 * kk],     a1 = pH[2 * kk];
        uint32_t a2 = pL[2 * kk + 1], a3 = pH[2 * kk + 1];
        #pragma unroll
        for (int p = 0; p < 8; p++) {
            int vr = p * 16 + ((lane >> 4) & 1) * 8 + (lane & 7);
            int vc = kk * 16 + ((lane >> 3) & 1) * 8;
            uint32_t b0, b1, b2, b3;
            ldsm4(b0, b1, b2, b3, vbase + (vr * KSTR + vc) * 2);
            mma_f16(o[2 * p],     a0, a1, a2, a3, b0, b1);
            mma_f16(o[2 * p + 1], a0, a1, a2, a3, b2, b3);
        }
    }
}

#define O_RESCALE(o, al1, al2)                                        \
    if (__any_sync(0xffffffffu, (al1 != 1.0f) || (al2 != 1.0f))) {    \
        _Pragma("unroll")                                             \
        for (int i = 0; i < 16; i++) {                                \
            o[i][0] *= al1; o[i][1] *= al1;                           \
            o[i][2] *= al2; o[i][3] *= al2;                           \
        }                                                             \
    }

__global__ __launch_bounds__(256, 1) void attn_kernel(float* __restrict__ out)
{
    extern __shared__ __align__(16) __half hsm[];
    const uint32_t uS = smem_u32(hsm);

    const int t = threadIdx.x, lane = t & 31, wid = t >> 5;
    const int b = blockIdx.y;
    const __half* Kg = g_k + (size_t)b * TT * HD;
    const __half* Vg = g_vt + (size_t)b * HD * TT;
    const int NQT = TT / 128;                 // 16

    #pragma unroll 1
    for (int pass = 0; pass < 2; pass++) {
        const int qtile = pass ? (NQT - 1 - (int)blockIdx.x) : (int)blockIdx.x;
        const int q0 = qtile * 128;
        const __half* Qg = g_q + ((size_t)b * TT + q0) * HD;

        __syncthreads();

        // ---- stage Q, extract fragments ----
        #pragma unroll
        for (int i = 0; i < 8; i++) {
            int idx = t + 256 * i;
            int row = idx >> 4, c8 = idx & 15;
            cp16(uS + (row * KSTR + c8 * 8) * 2, Qg + (size_t)row * HD + c8 * 8);
        }
        CP_COMMIT();
        CP_WAIT(0);
        __syncthreads();

        uint32_t qf[8][4];
        #pragma unroll
        for (int k0 = 0; k0 < 128; k0 += 16) {
            int row = wid * 16 + ((lane >> 3) & 1) * 8 + (lane & 7);
            int col = k0 + (lane >> 4) * 8;
            ldsm4(qf[k0 >> 4][0], qf[k0 >> 4][1], qf[k0 >> 4][2], qf[k0 >> 4][3],
                  uS + (row * KSTR + col) * 2);
        }
        __syncthreads();

        // ---- issue tile 0 ----
        #pragma unroll
        for (int i = 0; i < 8; i++) {
            int idx = t + 256 * i;
            int row = idx >> 4, c8 = idx & 15;
            cp16(uS + (row * KSTR + c8 * 8) * 2, Kg + (size_t)row * HD + c8 * 8);
            cp16(uS + VOFF_B + (row * KSTR + c8 * 8) * 2, Vg + (size_t)row * TT + c8 * 8);
        }
        CP_COMMIT();

        float o[16][4];
        #pragma unroll
        for (int i = 0; i < 16; i++)
            #pragma unroll
            for (int r = 0; r < 4; r++) o[i][r] = 0.0f;
        float m1 = -INFINITY, m2 = -INFINITY, l1 = 0.0f, l2 = 0.0f;

        const int qrow1 = q0 + wid * 16 + (lane >> 2);
        const int qrow2 = qrow1 + 8;

        for (int kt = 0; kt <= qtile; kt++) {
            const uint32_t uT = uS + (kt & 1) * STG_B;
            __syncthreads();
            if (kt < qtile) {
                const uint32_t uN = uS + ((kt + 1) & 1) * STG_B;
                const __half* Kn = Kg + (size_t)(kt + 1) * 128 * HD;
                const __half* Vn = Vg + (size_t)(kt + 1) * 128;
                #pragma unroll
                for (int i = 0; i < 8; i++) {
                    int idx = t + 256 * i;
                    int row = idx >> 4, c8 = idx & 15;
                    cp16(uN + (row * KSTR + c8 * 8) * 2, Kn + (size_t)row * HD + c8 * 8);
                    cp16(uN + VOFF_B + (row * KSTR + c8 * 8) * 2, Vn + (size_t)row * TT + c8 * 8);
                }
                CP_COMMIT();
                CP_WAIT(1);                 // tile kt resident, kt+1 in flight
            } else {
                CP_COMMIT();
                CP_WAIT(0);                 // final tile: full drain (no race)
            }
            __syncthreads();

            const bool dm = (kt == qtile);
            float s[8][4];
            uint32_t p0L[8], p0H[8], p1L[8], p1H[8];
            float al1, al2;

            // half 0
            attn_smma(s, qf, uT, lane);
            attn_softmax(s, p0L, p0H, m1, m2, l1, l2, al1, al2,
                         dm, kt * 128, qrow1, qrow2, lane);
            O_RESCALE(o, al1, al2);
            // half 1 scores interleave with PV0
            attn_smma(s, qf, uT + 64 * KSTR * 2, lane);
            attn_pv(o, p0L, p0H, uT + VOFF_B, lane);
            attn_softmax(s, p1L, p1H, m1, m2, l1, l2, al1, al2,
                         dm, kt * 128 + 64, qrow1, qrow2, lane);
            O_RESCALE(o, al1, al2);
            attn_pv(o, p1L, p1H, uT + VOFF_B + 64 * 2, lane);
        }

        // ---- epilogue: reduce per-thread l partials over the quad ----
        l1 += __shfl_xor_sync(0xffffffffu, l1, 1);
        l1 += __shfl_xor_sync(0xffffffffu, l1, 2);
        l2 += __shfl_xor_sync(0xffffffffu, l2, 1);
        l2 += __shfl_xor_sync(0xffffffffu, l2, 2);
        float inv1 = 1.0f / l1, inv2 = 1.0f / l2;
        float* Og = out + ((size_t)b * TT + q0) * HD;
        int r1 = wid * 16 + (lane >> 2);
        int pc = 2 * (lane & 3);
        #pragma unroll
        for (int nt = 0; nt < 16; nt++) {
            *(float2*)&Og[(size_t)r1 * HD + nt * 8 + pc] =
                make_float2(o[nt][0] * inv1, o[nt][1] * inv1);
            *(float2*)&Og[(size_t)(r1 + 8) * HD + nt * 8 + pc] =
                make_float2(o[nt][2] * inv2, o[nt][3] * inv2);
        }
    }
}

// ===========================================================================
extern "C" void kernel_launch(void* const* d_in, const int* in_sizes, int n_in,
                              void* d_out, int out_size)
{
    const float* x  = (const float*)d_in[0];
    const float* Wk = (const float*)d_in[1];
    const float* Wq = (const float*)d_in[2];
    const float* Wv = (const float*)d_in[3];
    float* out = (float*)d_out;

    prep_kernel<<<XBLKS + 384, 256>>>(x, Wk, Wq, Wv);

    noop_kernel<<<1, 32>>>();   // keep 4-launch config (capture lands on attn)

    cudaFuncSetAttribute(proj_kernel,
                         cudaFuncAttributeMaxDynamicSharedMemorySize, PROJ_SMEM);
    proj_kernel<<<768, 256, PROJ_SMEM>>>();

    cudaFuncSetAttribute(attn_kernel,
                         cudaFuncAttributeMaxDynamicSharedMemorySize, ATTN_SMEM);
    dim3 ga(TT / 256, BB);
    attn_kernel<<<ga, 256, ATTN_SMEM>>>(out);
}